// round 6
// baseline (speedup 1.0000x reference)
#include <cuda_runtime.h>
#include <cuda_fp16.h>
#include <mma.h>

using namespace nvcuda;

#define N_NODES 50000
#define N_EDGES 800000
#define IN_DIM  128
#define H_HEADS 4
#define F_DIM   32
#define HF      128      // H*F
#define OUT_ROW 160      // (H+1)*F
#define NEG_SLOPE 0.2f

// ---------------- device scratch (no allocs allowed) ----------------
__device__ __half g_el_mut [N_NODES * HF];   // fp16: attention-score path only
__device__ __half g_er_mut [N_NODES * HF];
__device__ float  g_el_self[N_NODES * HF];   // fp32: direct output path
__device__ float  g_ex     [N_EDGES * H_HEADS];
__device__ float  g_denom  [N_NODES * H_HEADS];
__device__ int    g_idx64;

// ---------------- helpers ----------------
__device__ __forceinline__ long load_index(const void* p, int e, int is64) {
    return is64 ? (long)((const long long*)p)[e] : (long)((const int*)p)[e];
}

// Zero ft region of output (cols 32..159 per node) and denom; detect index width.
__global__ void zero_kernel(float4* __restrict__ out, const int* __restrict__ src) {
    long i = (long)blockIdx.x * blockDim.x + threadIdx.x;
    if (i == 0) {
        int all0 = 1;
        #pragma unroll
        for (int k = 1; k < 16; k += 2) all0 &= (src[k] == 0);
        g_idx64 = all0;
    }
    if (i < (long)N_NODES * 32) {
        int n = (int)(i >> 5);
        int j = (int)(i & 31);
        out[(long)n * 40 + 8 + j] = make_float4(0.f, 0.f, 0.f, 0.f);
    }
    if (i < (N_NODES * H_HEADS) / 4) {
        ((float4*)g_denom)[i] = make_float4(0.f, 0.f, 0.f, 0.f);
    }
}

// ---------------- projection GEMM (tf32 tensor cores) ----------------
// C[M=50000, ncols] = feat[50000,128] @ W[128,ncols] + b
// Block: 64 M-rows x 128 N-cols, 8 warps as 4(M) x 2(N); each warp 16x64
// via 4 m16n16k8 wmma n-subtiles. A loaded from global (interior blocks) or
// smem-staged with bounds checks (boundary block). C staged through smem
// (buffer unioned with A staging), bias added, converted per destination.
#define PBM 64

__global__ __launch_bounds__(256, 2)
void proj_tc_kernel(const float* __restrict__ feat,
                    const float* __restrict__ Wsrc, const float* __restrict__ bsrc,
                    const float* __restrict__ Wdst, const float* __restrict__ bdst,
                    const float* __restrict__ Wself, const float* __restrict__ bself,
                    const float* __restrict__ Wlin, const float* __restrict__ blin,
                    float* __restrict__ out)
{
    __shared__ float sbuf[PBM * IN_DIM];   // 32KB: A staging OR C staging (time-disjoint)

    const float* W; const float* bias; int ncols;
    int ytile = blockIdx.y;
    if (ytile == 0)      { W = Wsrc;  bias = bsrc;  ncols = HF; }
    else if (ytile == 1) { W = Wdst;  bias = bdst;  ncols = HF; }
    else if (ytile == 2) { W = Wself; bias = bself; ncols = HF; }
    else                 { W = Wlin;  bias = blin;  ncols = F_DIM; }

    int t    = threadIdx.x;
    int wid  = t >> 5;
    int lane = t & 31;
    int warpM = wid & 3;       // 4 M-subtiles of 16
    int warpN = wid >> 2;      // 2 N-subtiles of 64
    int mOff  = warpM * 16;
    int nBase = warpN * 64;
    int rowBase = blockIdx.x * PBM;

    bool interior = (rowBase + PBM <= N_NODES);
    const float* Abase = feat + (long)rowBase * IN_DIM;
    if (!interior) {
        // stage A with bounds checks
        for (int idx = t; idx < PBM * IN_DIM / 4; idx += 256) {
            int r  = idx >> 5;
            int c4 = idx & 31;
            float4 v = make_float4(0.f, 0.f, 0.f, 0.f);
            int grow = rowBase + r;
            if (grow < N_NODES)
                v = ((const float4*)feat)[(long)grow * 32 + c4];
            ((float4*)sbuf)[idx] = v;
        }
        __syncthreads();
        Abase = sbuf;
    }

    wmma::fragment<wmma::accumulator, 16, 16, 8, float> c[4];
    #pragma unroll
    for (int s = 0; s < 4; s++) wmma::fill_fragment(c[s], 0.f);

    for (int k0 = 0; k0 < IN_DIM; k0 += 8) {
        wmma::fragment<wmma::matrix_a, 16, 16, 8, wmma::precision::tf32, wmma::row_major> a;
        wmma::load_matrix_sync(a, Abase + (long)mOff * IN_DIM + k0, IN_DIM);
        #pragma unroll
        for (int i = 0; i < a.num_elements; i++)
            a.x[i] = wmma::__float_to_tf32(a.x[i]);

        #pragma unroll
        for (int s = 0; s < 4; s++) {
            int n = nBase + s * 16;
            if (n < ncols) {
                wmma::fragment<wmma::matrix_b, 16, 16, 8, wmma::precision::tf32, wmma::row_major> b;
                wmma::load_matrix_sync(b, W + (long)k0 * ncols + n, ncols);
                #pragma unroll
                for (int i = 0; i < b.num_elements; i++)
                    b.x[i] = wmma::__float_to_tf32(b.x[i]);
                wmma::mma_sync(c[s], a, b, c[s]);
            }
        }
    }

    // reuse sbuf as C staging: per-warp 16x64 region
    __syncthreads();
    float* Cw = sbuf + wid * 16 * 64;
    #pragma unroll
    for (int s = 0; s < 4; s++)
        if (nBase + s * 16 < ncols)
            wmma::store_matrix_sync(Cw + s * 16, c[s], 64, wmma::mem_row_major);
    __syncwarp();   // each warp reads only its own staging region

    // epilogue: 2 lanes per row, each lane covers 32 cols (8 float4)
    int r = lane >> 1;
    int grow = rowBase + mOff + r;
    if (grow < N_NODES) {
        #pragma unroll
        for (int q = 0; q < 8; q++) {
            int cc   = (lane & 1) * 32 + q * 4;
            int gcol = nBase + cc;
            if (gcol >= ncols) break;
            float4 v  = *((float4*)&Cw[r * 64 + cc]);
            float4 b4 = ((const float4*)bias)[gcol >> 2];
            v.x += b4.x; v.y += b4.y; v.z += b4.z; v.w += b4.w;
            if (ytile == 0 || ytile == 1) {
                __half2 h0 = __floats2half2_rn(v.x, v.y);
                __half2 h1 = __floats2half2_rn(v.z, v.w);
                uint2 u;
                *((__half2*)&u.x) = h0;
                *((__half2*)&u.y) = h1;
                __half* base = (ytile == 0) ? g_el_mut : g_er_mut;
                ((uint2*)base)[(long)grow * 32 + (gcol >> 2)] = u;
            } else if (ytile == 2) {
                ((float4*)g_el_self)[(long)grow * 32 + (gcol >> 2)] = v;
            } else {
                ((float4*)out)[(long)grow * 40 + (gcol >> 2)] = v;  // feat_lin -> out[:, 0, :]
            }
        }
    }
}

// ---------------- edge scores + denom ----------------
// FOUR edges per warp (8 gathers in flight); lane l covers features 4l..4l+3,
// head = l>>3. All math in half2; leaky(x) = max(x, 0.2x) since slope < 1.
__global__ __launch_bounds__(256)
void edge_score_kernel(const void* __restrict__ srcp, const void* __restrict__ dstp,
                       const float* __restrict__ attn)
{
    int warp = (blockIdx.x * blockDim.x + threadIdx.x) >> 5;
    int lane = threadIdx.x & 31;
    int e0 = warp * 4;
    if (e0 >= N_EDGES) return;
    int is64 = g_idx64;

    long s[4], d[4];
    #pragma unroll
    for (int i = 0; i < 4; i++) {
        s[i] = load_index(srcp, e0 + i, is64);
        d[i] = load_index(dstp, e0 + i, is64);
    }

    // attn for this lane's 4 features, as two half2 (loop-invariant)
    float4 atf = ((const float4*)attn)[lane];
    __half2 a0 = __floats2half2_rn(atf.x, atf.y);
    __half2 a1 = __floats2half2_rn(atf.z, atf.w);
    const __half2 slope = __floats2half2_rn(NEG_SLOPE, NEG_SLOPE);

    // 8 independent LDG.64 gathers in flight
    uint2 ul[4], ur[4];
    #pragma unroll
    for (int i = 0; i < 4; i++) {
        ul[i] = ((const uint2*)g_el_mut)[s[i] * 32 + lane];
        ur[i] = ((const uint2*)g_er_mut)[d[i] * 32 + lane];
    }

    int h = lane >> 3;
    bool leader = (lane & 7) == 0;

    #pragma unroll
    for (int i = 0; i < 4; i++) {
        __half2 x0 = __hadd2(*((__half2*)&ul[i].x), *((__half2*)&ur[i].x));
        __half2 x1 = __hadd2(*((__half2*)&ul[i].y), *((__half2*)&ur[i].y));
        // leaky relu: max(x, 0.2x)
        x0 = __hmax2(x0, __hmul2(x0, slope));
        x1 = __hmax2(x1, __hmul2(x1, slope));
        // dot with attn
        __half2 p2 = __hfma2(x1, a1, __hmul2(x0, a0));
        float2 pf = __half22float2(p2);
        float p = pf.x + pf.y;

        // reduce within 8-lane head group
        p += __shfl_xor_sync(0xFFFFFFFFu, p, 4);
        p += __shfl_xor_sync(0xFFFFFFFFu, p, 2);
        p += __shfl_xor_sync(0xFFFFFFFFu, p, 1);

        if (leader) {
            // softmax-invariant: skip segment_max (scores are O(1) by construction)
            float e = __expf(p);
            g_ex[(long)(e0 + i) * 4 + h] = e;
            float* dptr = &g_denom[d[i] * 4 + h];
            asm volatile("red.global.add.f32 [%0], %1;"
                         :: "l"(dptr), "f"(e) : "memory");
        }
    }
}

// ---------------- weighted aggregation ----------------
// FOUR edges per warp.
__global__ __launch_bounds__(256)
void aggregate_kernel(const void* __restrict__ srcp, const void* __restrict__ dstp,
                      float* __restrict__ out)
{
    int warp = (blockIdx.x * blockDim.x + threadIdx.x) >> 5;
    int lane = threadIdx.x & 31;
    int e0 = warp * 4;
    if (e0 >= N_EDGES) return;
    int is64 = g_idx64;

    long s[4], d[4];
    #pragma unroll
    for (int i = 0; i < 4; i++) {
        s[i] = load_index(srcp, e0 + i, is64);
        d[i] = load_index(dstp, e0 + i, is64);
    }

    int h = lane >> 3;
    float ex[4], den[4];
    float4 el[4];
    #pragma unroll
    for (int i = 0; i < 4; i++) {
        ex[i]  = g_ex[(long)(e0 + i) * 4 + h];
        den[i] = g_denom[d[i] * 4 + h];
        el[i]  = ((const float4*)g_el_self)[s[i] * 32 + lane];
    }

    #pragma unroll
    for (int i = 0; i < 4; i++) {
        float a = ex[i] / den[i];
        float4 m = make_float4(el[i].x * a, el[i].y * a, el[i].z * a, el[i].w * a);
        // ft region: out[d, 1+h, f] == out + d*160 + 32 + lane*4
        float* p = out + (long)d[i] * OUT_ROW + 32 + lane * 4;
        asm volatile("red.global.add.v4.f32 [%0], {%1,%2,%3,%4};"
                     :: "l"(p), "f"(m.x), "f"(m.y), "f"(m.z), "f"(m.w) : "memory");
    }
}

// ---------------- stream fork resources (host-side, static init) ----------------
struct ForkResources {
    cudaStream_t s2;
    cudaEvent_t  e0, eZ;
    bool ok;
    ForkResources() : ok(false) {
        if (cudaStreamCreateWithFlags(&s2, cudaStreamNonBlocking) != cudaSuccess) return;
        if (cudaEventCreateWithFlags(&e0, cudaEventDisableTiming) != cudaSuccess) return;
        if (cudaEventCreateWithFlags(&eZ, cudaEventDisableTiming) != cudaSuccess) return;
        ok = true;
    }
};
static ForkResources g_fork;

// ---------------- launch ----------------
extern "C" void kernel_launch(void* const* d_in, const int* in_sizes, int n_in,
                              void* d_out, int out_size)
{
    const float* feat  = (const float*)d_in[0];
    const float* Wsrc  = (const float*)d_in[1];
    const float* bsrc  = (const float*)d_in[2];
    const float* Wdst  = (const float*)d_in[3];
    const float* bdst  = (const float*)d_in[4];
    const float* Wself = (const float*)d_in[5];
    const float* bself = (const float*)d_in[6];
    const float* Wlin  = (const float*)d_in[7];
    const float* blin  = (const float*)d_in[8];
    const float* attn  = (const float*)d_in[9];
    const void*  src   = d_in[10];
    const void*  dst   = d_in[11];
    float* out = (float*)d_out;

    dim3 pg((N_NODES + PBM - 1) / PBM, 4);
    int edgeBlocks = (N_EDGES / 4 + 7) / 8;   // 4 edges/warp, 8 warps/block

    if (g_fork.ok) {
        // legal fork: s2 joins capture via event wait BEFORE receiving work
        cudaEventRecord(g_fork.e0, 0);
        cudaStreamWaitEvent(g_fork.s2, g_fork.e0, 0);

        // s2: zero + detect (overlaps proj)
        zero_kernel<<<(N_NODES * 32 + 255) / 256, 256, 0, g_fork.s2>>>(
            (float4*)out, (const int*)src);
        cudaEventRecord(g_fork.eZ, g_fork.s2);

        // main: all 4 projections on tensor cores
        proj_tc_kernel<<<pg, 256>>>(feat, Wsrc, bsrc, Wdst, bdst,
                                    Wself, bself, Wlin, blin, out);

        // main: edge_score (needs proj + zero/detect)
        cudaStreamWaitEvent(0, g_fork.eZ, 0);
        edge_score_kernel<<<edgeBlocks, 256>>>(src, dst, attn);
        aggregate_kernel<<<edgeBlocks, 256>>>(src, dst, out);
    } else {
        zero_kernel<<<(N_NODES * 32 + 255) / 256, 256>>>((float4*)out, (const int*)src);
        proj_tc_kernel<<<pg, 256>>>(feat, Wsrc, bsrc, Wdst, bdst,
                                    Wself, bself, Wlin, blin, out);
        edge_score_kernel<<<edgeBlocks, 256>>>(src, dst, attn);
        aggregate_kernel<<<edgeBlocks, 256>>>(src, dst, out);
    }
}

// round 7
// speedup vs baseline: 1.3251x; 1.3251x over previous
#include <cuda_runtime.h>
#include <cuda_fp16.h>
#include <mma.h>

using namespace nvcuda;

#define N_NODES 50000
#define N_PAD   50048    // 391 * 128, padded for wmma tiles
#define N_EDGES 800000
#define IN_DIM  128
#define H_HEADS 4
#define F_DIM   32
#define HF      128      // H*F
#define OUT_ROW 160      // (H+1)*F
#define NEG_SLOPE 0.2f

// ---------------- device scratch (no allocs allowed) ----------------
__device__ __half g_el_mut   [N_NODES * HF];  // fp16: attention-score path
__device__ __half g_er_mut   [N_NODES * HF];
__device__ __half g_el_self_h[N_NODES * HF];  // fp16 storage; fp32 math in aggregate
__device__ __half g_feat_h   [N_PAD * IN_DIM];   // half copy of feat (padded)
__device__ __half g_Wh       [2 * IN_DIM * HF];  // half copies of Wsrc, Wdst
__device__ float  g_ex       [N_EDGES * H_HEADS];
__device__ float  g_denom    [N_NODES * H_HEADS];
__device__ int    g_idx64;

// ---------------- helpers ----------------
__device__ __forceinline__ long load_index(const void* p, int e, int is64) {
    return is64 ? (long)((const long long*)p)[e] : (long)((const int*)p)[e];
}

// Zero ft region of output (cols 32..159 per node) and denom; detect index width.
__global__ void zero_kernel(float4* __restrict__ out, const int* __restrict__ src) {
    long i = (long)blockIdx.x * blockDim.x + threadIdx.x;
    if (i == 0) {
        int all0 = 1;
        #pragma unroll
        for (int k = 1; k < 16; k += 2) all0 &= (src[k] == 0);
        g_idx64 = all0;
    }
    if (i < (long)N_NODES * 32) {
        int n = (int)(i >> 5);
        int j = (int)(i & 31);
        out[(long)n * 40 + 8 + j] = make_float4(0.f, 0.f, 0.f, 0.f);
    }
    if (i < (N_NODES * H_HEADS) / 4) {
        ((float4*)g_denom)[i] = make_float4(0.f, 0.f, 0.f, 0.f);
    }
}

// ---------------- fp32 -> fp16 conversion of feat, Wsrc, Wdst ----------------
#define FEAT_F4  (N_PAD * 32)            // float4 slots for padded feat
#define FEATR_F4 (N_NODES * 32)          // real float4 slots
#define W_F4     (IN_DIM * HF / 4)       // 4096 per weight matrix
#define CONV_F4  (FEAT_F4 + 2 * W_F4)

__global__ void convert_kernel(const float* __restrict__ feat,
                               const float* __restrict__ Wsrc,
                               const float* __restrict__ Wdst) {
    int i = blockIdx.x * blockDim.x + threadIdx.x;
    if (i >= CONV_F4) return;
    float4 v = make_float4(0.f, 0.f, 0.f, 0.f);
    uint2* dst;
    if (i < FEAT_F4) {
        if (i < FEATR_F4) v = ((const float4*)feat)[i];
        dst = ((uint2*)g_feat_h) + i;
    } else {
        int j = i - FEAT_F4;
        v = (j < W_F4) ? ((const float4*)Wsrc)[j]
                       : ((const float4*)Wdst)[j - W_F4];
        dst = ((uint2*)g_Wh) + j;
    }
    uint2 u;
    *((__half2*)&u.x) = __floats2half2_rn(v.x, v.y);
    *((__half2*)&u.y) = __floats2half2_rn(v.z, v.w);
    *dst = u;
}

// ---------------- projA: el_mut / er_mut via fp16 HMMA ----------------
// Block = 128 M x 128 N, 8 warps as 4(M) x 2(N); warp tile 32 x 64.
// A frags from g_feat_h (global, half, row-major), B frags from g_Wh.
// fp32 accumulate; epilogue adds bias and writes half.
__global__ __launch_bounds__(256, 1)
void projA_wmma_kernel(const float* __restrict__ bsrc,
                       const float* __restrict__ bdst)
{
    __shared__ float cstage[8][16 * 20];   // per-warp 16x16 f32 staging (ldm=20)

    int ytile = blockIdx.y;
    const float* bias = ytile ? bdst : bsrc;
    const __half* Wh = g_Wh + (long)ytile * IN_DIM * HF;
    __half* dstbuf = ytile ? g_er_mut : g_el_mut;

    int wid  = threadIdx.x >> 5;
    int lane = threadIdx.x & 31;
    int warpM = wid & 3;        // 4 M-subtiles of 32
    int warpN = wid >> 2;       // 2 N-subtiles of 64
    int rowBase = blockIdx.x * 128 + warpM * 32;
    int nBase   = warpN * 64;

    wmma::fragment<wmma::accumulator, 16, 16, 16, float> acc[2][4];
    #pragma unroll
    for (int mi = 0; mi < 2; mi++)
        #pragma unroll
        for (int s = 0; s < 4; s++) wmma::fill_fragment(acc[mi][s], 0.f);

    #pragma unroll
    for (int k0 = 0; k0 < IN_DIM; k0 += 16) {
        wmma::fragment<wmma::matrix_a, 16, 16, 16, __half, wmma::row_major> a[2];
        wmma::load_matrix_sync(a[0], g_feat_h + (long)rowBase * IN_DIM + k0, IN_DIM);
        wmma::load_matrix_sync(a[1], g_feat_h + (long)(rowBase + 16) * IN_DIM + k0, IN_DIM);
        #pragma unroll
        for (int s = 0; s < 4; s++) {
            wmma::fragment<wmma::matrix_b, 16, 16, 16, __half, wmma::row_major> b;
            wmma::load_matrix_sync(b, Wh + (long)k0 * HF + nBase + s * 16, HF);
            wmma::mma_sync(acc[0][s], a[0], b, acc[0][s]);
            wmma::mma_sync(acc[1][s], a[1], b, acc[1][s]);
        }
    }

    // epilogue: stage each 16x16 frag through smem, add bias, write half
    int r  = lane >> 1;          // 0..15 row in frag
    int hc = lane & 1;           // half-row: cols hc*8..hc*8+7
    #pragma unroll
    for (int mi = 0; mi < 2; mi++) {
        #pragma unroll
        for (int s = 0; s < 4; s++) {
            wmma::store_matrix_sync(&cstage[wid][0], acc[mi][s], 20, wmma::mem_row_major);
            __syncwarp();
            int grow = rowBase + mi * 16 + r;
            if (grow < N_NODES) {
                int ncol = nBase + s * 16 + hc * 8;
                float f[8];
                #pragma unroll
                for (int j = 0; j < 8; j++)
                    f[j] = cstage[wid][r * 20 + hc * 8 + j] + bias[ncol + j];
                uint4 u;
                *((__half2*)&u.x) = __floats2half2_rn(f[0], f[1]);
                *((__half2*)&u.y) = __floats2half2_rn(f[2], f[3]);
                *((__half2*)&u.z) = __floats2half2_rn(f[4], f[5]);
                *((__half2*)&u.w) = __floats2half2_rn(f[6], f[7]);
                ((uint4*)dstbuf)[(long)grow * 16 + (ncol >> 3)] = u;
            }
            __syncwarp();
        }
    }
}

// ---------------- projB: el_self / feat_lin, scalar fp32 GEMM ----------------
#define BM 64
#define BK 32

__global__ __launch_bounds__(256, 2)
void projB_kernel(const float* __restrict__ feat,
                  const float* __restrict__ Wself, const float* __restrict__ bself,
                  const float* __restrict__ Wlin, const float* __restrict__ blin,
                  float* __restrict__ out)
{
    __shared__ float As[BK][BM + 4];
    __shared__ float Bs[BK][HF];

    const float* W; const float* bias; int ncols;
    int ytile = blockIdx.y + 2;
    if (ytile == 2) { W = Wself; bias = bself; ncols = HF; }
    else            { W = Wlin;  bias = blin;  ncols = F_DIM; }

    int t  = threadIdx.x;
    int tx = t & 31;
    int ty = t >> 5;
    int rowBase = blockIdx.x * BM;

    float acc[8][4];
    #pragma unroll
    for (int i = 0; i < 8; i++)
        #pragma unroll
        for (int j = 0; j < 4; j++) acc[i][j] = 0.f;

    for (int k0 = 0; k0 < IN_DIM; k0 += BK) {
        #pragma unroll
        for (int i = 0; i < 2; i++) {
            int id = t + i * 256;
            int r  = id >> 3;
            int kq = id & 7;
            int grow = rowBase + r;
            float4 v = make_float4(0.f, 0.f, 0.f, 0.f);
            if (grow < N_NODES)
                v = ((const float4*)feat)[(long)grow * 32 + (k0 >> 2) + kq];
            As[kq * 4 + 0][r] = v.x;
            As[kq * 4 + 1][r] = v.y;
            As[kq * 4 + 2][r] = v.z;
            As[kq * 4 + 3][r] = v.w;
        }
        #pragma unroll
        for (int i = 0; i < 4; i++) {
            int id = t + i * 256;
            int kk = id >> 5;
            int c4 = id & 31;
            float4 v = make_float4(0.f, 0.f, 0.f, 0.f);
            if (c4 * 4 < ncols)
                v = ((const float4*)W)[(long)(k0 + kk) * (ncols / 4) + c4];
            *((float4*)&Bs[kk][c4 * 4]) = v;
        }
        __syncthreads();

        #pragma unroll
        for (int k = 0; k < BK; k++) {
            float4 a0 = *((const float4*)&As[k][ty * 8]);
            float4 a1 = *((const float4*)&As[k][ty * 8 + 4]);
            float4 b  = *((const float4*)&Bs[k][tx * 4]);
            float a[8] = {a0.x, a0.y, a0.z, a0.w, a1.x, a1.y, a1.z, a1.w};
            #pragma unroll
            for (int i = 0; i < 8; i++) {
                acc[i][0] += a[i] * b.x;
                acc[i][1] += a[i] * b.y;
                acc[i][2] += a[i] * b.z;
                acc[i][3] += a[i] * b.w;
            }
        }
        __syncthreads();
    }

    float4 b4 = make_float4(0.f, 0.f, 0.f, 0.f);
    if (tx * 4 < ncols) b4 = ((const float4*)bias)[tx];

    #pragma unroll
    for (int i = 0; i < 8; i++) {
        int grow = rowBase + ty * 8 + i;
        if (grow >= N_NODES) continue;
        float4 v = make_float4(acc[i][0] + b4.x, acc[i][1] + b4.y,
                               acc[i][2] + b4.z, acc[i][3] + b4.w);
        if (ytile == 2) {
            uint2 u;
            *((__half2*)&u.x) = __floats2half2_rn(v.x, v.y);
            *((__half2*)&u.y) = __floats2half2_rn(v.z, v.w);
            ((uint2*)g_el_self_h)[(long)grow * 32 + tx] = u;
        } else if (tx < 8) {
            ((float4*)out)[(long)grow * 40 + tx] = v;  // feat_lin -> out[:, 0, :]
        }
    }
}

// ---------------- edge scores + denom ----------------
// FOUR edges per warp; lane l covers features 4l..4l+3, head = l>>3.
__global__ __launch_bounds__(256)
void edge_score_kernel(const void* __restrict__ srcp, const void* __restrict__ dstp,
                       const float* __restrict__ attn)
{
    int warp = (blockIdx.x * blockDim.x + threadIdx.x) >> 5;
    int lane = threadIdx.x & 31;
    int e0 = warp * 4;
    if (e0 >= N_EDGES) return;
    int is64 = g_idx64;

    long s[4], d[4];
    #pragma unroll
    for (int i = 0; i < 4; i++) {
        s[i] = load_index(srcp, e0 + i, is64);
        d[i] = load_index(dstp, e0 + i, is64);
    }

    float4 atf = ((const float4*)attn)[lane];
    __half2 a0 = __floats2half2_rn(atf.x, atf.y);
    __half2 a1 = __floats2half2_rn(atf.z, atf.w);
    const __half2 slope = __floats2half2_rn(NEG_SLOPE, NEG_SLOPE);

    uint2 ul[4], ur[4];
    #pragma unroll
    for (int i = 0; i < 4; i++) {
        ul[i] = ((const uint2*)g_el_mut)[s[i] * 32 + lane];
        ur[i] = ((const uint2*)g_er_mut)[d[i] * 32 + lane];
    }

    int h = lane >> 3;
    bool leader = (lane & 7) == 0;

    #pragma unroll
    for (int i = 0; i < 4; i++) {
        __half2 x0 = __hadd2(*((__half2*)&ul[i].x), *((__half2*)&ur[i].x));
        __half2 x1 = __hadd2(*((__half2*)&ul[i].y), *((__half2*)&ur[i].y));
        x0 = __hmax2(x0, __hmul2(x0, slope));          // leaky = max(x, 0.2x)
        x1 = __hmax2(x1, __hmul2(x1, slope));
        __half2 p2 = __hfma2(x1, a1, __hmul2(x0, a0));
        float2 pf = __half22float2(p2);
        float p = pf.x + pf.y;

        p += __shfl_xor_sync(0xFFFFFFFFu, p, 4);
        p += __shfl_xor_sync(0xFFFFFFFFu, p, 2);
        p += __shfl_xor_sync(0xFFFFFFFFu, p, 1);

        if (leader) {
            float e = __expf(p);   // softmax-invariant: segment_max skipped
            g_ex[(long)(e0 + i) * 4 + h] = e;
            float* dptr = &g_denom[d[i] * 4 + h];
            asm volatile("red.global.add.f32 [%0], %1;"
                         :: "l"(dptr), "f"(e) : "memory");
        }
    }
}

// ---------------- weighted aggregation ----------------
// FOUR edges per warp; fp16 gathers, fp32 math + RED.
__global__ __launch_bounds__(256)
void aggregate_kernel(const void* __restrict__ srcp, const void* __restrict__ dstp,
                      float* __restrict__ out)
{
    int warp = (blockIdx.x * blockDim.x + threadIdx.x) >> 5;
    int lane = threadIdx.x & 31;
    int e0 = warp * 4;
    if (e0 >= N_EDGES) return;
    int is64 = g_idx64;

    long s[4], d[4];
    #pragma unroll
    for (int i = 0; i < 4; i++) {
        s[i] = load_index(srcp, e0 + i, is64);
        d[i] = load_index(dstp, e0 + i, is64);
    }

    int h = lane >> 3;
    float ex[4], den[4];
    uint2 el[4];
    #pragma unroll
    for (int i = 0; i < 4; i++) {
        ex[i]  = g_ex[(long)(e0 + i) * 4 + h];
        den[i] = g_denom[d[i] * 4 + h];
        el[i]  = ((const uint2*)g_el_self_h)[s[i] * 32 + lane];
    }

    #pragma unroll
    for (int i = 0; i < 4; i++) {
        float a = ex[i] / den[i];
        float2 f0 = __half22float2(*((__half2*)&el[i].x));
        float2 f1 = __half22float2(*((__half2*)&el[i].y));
        float4 m = make_float4(f0.x * a, f0.y * a, f1.x * a, f1.y * a);
        float* p = out + (long)d[i] * OUT_ROW + 32 + lane * 4;
        asm volatile("red.global.add.v4.f32 [%0], {%1,%2,%3,%4};"
                     :: "l"(p), "f"(m.x), "f"(m.y), "f"(m.z), "f"(m.w) : "memory");
    }
}

// ---------------- stream fork resources (host-side, static init) ----------------
struct ForkResources {
    cudaStream_t s2;
    cudaEvent_t  e0, eZ, e2;
    bool ok;
    ForkResources() : ok(false) {
        if (cudaStreamCreateWithFlags(&s2, cudaStreamNonBlocking) != cudaSuccess) return;
        if (cudaEventCreateWithFlags(&e0, cudaEventDisableTiming) != cudaSuccess) return;
        if (cudaEventCreateWithFlags(&eZ, cudaEventDisableTiming) != cudaSuccess) return;
        if (cudaEventCreateWithFlags(&e2, cudaEventDisableTiming) != cudaSuccess) return;
        ok = true;
    }
};
static ForkResources g_fork;

// ---------------- launch ----------------
extern "C" void kernel_launch(void* const* d_in, const int* in_sizes, int n_in,
                              void* d_out, int out_size)
{
    const float* feat  = (const float*)d_in[0];
    const float* Wsrc  = (const float*)d_in[1];
    const float* bsrc  = (const float*)d_in[2];
    const float* Wdst  = (const float*)d_in[3];
    const float* bdst  = (const float*)d_in[4];
    const float* Wself = (const float*)d_in[5];
    const float* bself = (const float*)d_in[6];
    const float* Wlin  = (const float*)d_in[7];
    const float* blin  = (const float*)d_in[8];
    const float* attn  = (const float*)d_in[9];
    const void*  src   = d_in[10];
    const void*  dst   = d_in[11];
    float* out = (float*)d_out;

    dim3 pgA(N_PAD / 128, 2);                       // projA wmma
    dim3 pgB((N_NODES + BM - 1) / BM, 2);           // projB scalar
    int convBlocks = (CONV_F4 + 255) / 256;
    int edgeBlocks = (N_EDGES / 4 + 7) / 8;         // 4 edges/warp, 8 warps/block

    if (g_fork.ok) {
        // legal fork: s2 joins capture via event wait BEFORE receiving work
        cudaEventRecord(g_fork.e0, 0);
        cudaStreamWaitEvent(g_fork.s2, g_fork.e0, 0);

        // s2: zero + detect, then projB (el_self_h, feat_lin)
        zero_kernel<<<(N_NODES * 32 + 255) / 256, 256, 0, g_fork.s2>>>(
            (float4*)out, (const int*)src);
        cudaEventRecord(g_fork.eZ, g_fork.s2);
        projB_kernel<<<pgB, 256, 0, g_fork.s2>>>(feat, Wself, bself, Wlin, blin, out);
        cudaEventRecord(g_fork.e2, g_fork.s2);

        // main: convert then projA on tensor cores
        convert_kernel<<<convBlocks, 256>>>(feat, Wsrc, Wdst);
        projA_wmma_kernel<<<pgA, 256>>>(bsrc, bdst);

        // main: edge_score (needs projA + zero/detect)
        cudaStreamWaitEvent(0, g_fork.eZ, 0);
        edge_score_kernel<<<edgeBlocks, 256>>>(src, dst, attn);

        // join projB before aggregate
        cudaStreamWaitEvent(0, g_fork.e2, 0);
        aggregate_kernel<<<edgeBlocks, 256>>>(src, dst, out);
    } else {
        zero_kernel<<<(N_NODES * 32 + 255) / 256, 256>>>((float4*)out, (const int*)src);
        convert_kernel<<<convBlocks, 256>>>(feat, Wsrc, Wdst);
        projA_wmma_kernel<<<pgA, 256>>>(bsrc, bdst);
        projB_kernel<<<pgB, 256>>>(feat, Wself, bself, Wlin, blin, out);
        edge_score_kernel<<<edgeBlocks, 256>>>(src, dst, attn);
        aggregate_kernel<<<edgeBlocks, 256>>>(src, dst, out);
    }
}

// round 8
// speedup vs baseline: 1.6786x; 1.2668x over previous
#include <cuda_runtime.h>
#include <cuda_fp16.h>
#include <mma.h>

using namespace nvcuda;

#define N_NODES 50000
#define N_EDGES 800000
#define IN_DIM  128
#define H_HEADS 4
#define F_DIM   32
#define HF      128      // H*F
#define OUT_ROW 160      // (H+1)*F
#define NEG_SLOPE 0.2f

// ---------------- device scratch (no allocs allowed) ----------------
__device__ __half g_el_mut   [N_NODES * HF];  // fp16: attention-score path
__device__ __half g_er_mut   [N_NODES * HF];
__device__ __half g_el_self_h[N_NODES * HF];  // fp16 storage; fp32 math downstream
__device__ float  g_ex       [N_EDGES * H_HEADS];
__device__ float  g_denom    [N_NODES * H_HEADS];
__device__ int    g_idx64;

// ---------------- helpers ----------------
__device__ __forceinline__ long load_index(const void* p, int e, int is64) {
    return is64 ? (long)((const long long*)p)[e] : (long)((const int*)p)[e];
}

// Zero ft region of output (cols 32..159 per node) and denom; detect index width.
__global__ void zero_kernel(float4* __restrict__ out, const int* __restrict__ src) {
    long i = (long)blockIdx.x * blockDim.x + threadIdx.x;
    if (i == 0) {
        int all0 = 1;
        #pragma unroll
        for (int k = 1; k < 16; k += 2) all0 &= (src[k] == 0);
        g_idx64 = all0;
    }
    if (i < (long)N_NODES * 32) {
        int n = (int)(i >> 5);
        int j = (int)(i & 31);
        out[(long)n * 40 + 8 + j] = make_float4(0.f, 0.f, 0.f, 0.f);
    }
    if (i < (N_NODES * H_HEADS) / 4) {
        ((float4*)g_denom)[i] = make_float4(0.f, 0.f, 0.f, 0.f);
    }
}

// ---------------- projW: el_mut / er_mut / el_self via fp16 HMMA ----------------
// Block = 128 M-rows x 128 N-cols, 8 warps; warp tile = 16 M x 128 N.
// A (feat tile) and B (full W) staged in smem as half (stride 136 = 272B,
// 16B-multiple for LDSM), converted from fp32 during staging.
// fp32 accumulate; epilogue restages through smem (reused), adds bias, writes half.
#define SA_STRIDE 136
#define SA_BYTES  (128 * SA_STRIDE * 2)      // 34816 per tile

__global__ __launch_bounds__(256, 2)
void projW_kernel(const float* __restrict__ feat,
                  const float* __restrict__ Wsrc, const float* __restrict__ bsrc,
                  const float* __restrict__ Wdst, const float* __restrict__ bdst,
                  const float* __restrict__ Wself, const float* __restrict__ bself)
{
    __shared__ __align__(16) unsigned char sraw[2 * SA_BYTES];   // 69632 B
    __half* As = (__half*)sraw;
    __half* Bs = (__half*)(sraw + SA_BYTES);
    float*  Cst = (float*)sraw;              // epilogue staging (time-disjoint)

    const float* W; const float* bias; __half* dstbuf;
    int ytile = blockIdx.y;
    if (ytile == 0)      { W = Wsrc;  bias = bsrc;  dstbuf = g_el_mut; }
    else if (ytile == 1) { W = Wdst;  bias = bdst;  dstbuf = g_er_mut; }
    else                 { W = Wself; bias = bself; dstbuf = g_el_self_h; }

    int t    = threadIdx.x;
    int wid  = t >> 5;
    int lane = t & 31;
    int rowBase = blockIdx.x * 128;

    // stage A (feat tile, fp32 -> half) and B (W, fp32 -> half)
    #pragma unroll
    for (int i = 0; i < 8; i++) {
        int idx = t + i * 256;            // 0..2047 float4 slots
        int r   = idx >> 4;               // row 0..127
        int c4  = idx & 15;               // which 8-col group? No: 16 float4 = 64... 
        // 128 cols = 32 float4 per row; 2048 slots / 128 rows = 16 slots/row -> 
        // each slot covers 8 cols via TWO float4 reads
        int c8  = c4;                     // 16 groups of 8 cols
        int grow = rowBase + r;
        float4 v0 = make_float4(0.f, 0.f, 0.f, 0.f);
        float4 v1 = make_float4(0.f, 0.f, 0.f, 0.f);
        if (grow < N_NODES) {
            v0 = ((const float4*)feat)[(long)grow * 32 + c8 * 2];
            v1 = ((const float4*)feat)[(long)grow * 32 + c8 * 2 + 1];
        }
        uint4 u;
        *((__half2*)&u.x) = __floats2half2_rn(v0.x, v0.y);
        *((__half2*)&u.y) = __floats2half2_rn(v0.z, v0.w);
        *((__half2*)&u.z) = __floats2half2_rn(v1.x, v1.y);
        *((__half2*)&u.w) = __floats2half2_rn(v1.z, v1.w);
        *((uint4*)&As[r * SA_STRIDE + c8 * 8]) = u;

        // B: same indexing over W (always full 128x128)
        float4 w0 = ((const float4*)W)[idx * 2];
        float4 w1 = ((const float4*)W)[idx * 2 + 1];
        uint4 uw;
        *((__half2*)&uw.x) = __floats2half2_rn(w0.x, w0.y);
        *((__half2*)&uw.y) = __floats2half2_rn(w0.z, w0.w);
        *((__half2*)&uw.z) = __floats2half2_rn(w1.x, w1.y);
        *((__half2*)&uw.w) = __floats2half2_rn(w1.z, w1.w);
        *((uint4*)&Bs[r * SA_STRIDE + c8 * 8]) = uw;
    }
    __syncthreads();

    // compute: warp wid owns rows wid*16..wid*16+15, all 128 cols (8 n-frags)
    wmma::fragment<wmma::accumulator, 16, 16, 16, float> acc[8];
    #pragma unroll
    for (int n = 0; n < 8; n++) wmma::fill_fragment(acc[n], 0.f);

    #pragma unroll
    for (int k0 = 0; k0 < IN_DIM; k0 += 16) {
        wmma::fragment<wmma::matrix_a, 16, 16, 16, __half, wmma::row_major> a;
        wmma::load_matrix_sync(a, As + wid * 16 * SA_STRIDE + k0, SA_STRIDE);
        #pragma unroll
        for (int n = 0; n < 8; n++) {
            wmma::fragment<wmma::matrix_b, 16, 16, 16, __half, wmma::row_major> b;
            wmma::load_matrix_sync(b, Bs + k0 * SA_STRIDE + n * 16, SA_STRIDE);
            wmma::mma_sync(acc[n], a, b, acc[n]);
        }
    }

    // epilogue: restage through smem (reuses As/Bs memory), add bias, write half
    __syncthreads();
    float* cw = Cst + wid * 16 * 128;     // per-warp 16x128 f32 region (8KB)
    #pragma unroll
    for (int n = 0; n < 8; n++)
        wmma::store_matrix_sync(cw + n * 16, acc[n], 128, wmma::mem_row_major);
    __syncwarp();

    int r  = lane >> 1;                    // 0..15
    int hc = lane & 1;                     // col half: hc*64..hc*64+63
    int grow = rowBase + wid * 16 + r;
    if (grow < N_NODES) {
        const float* crow = cw + r * 128 + hc * 64;
        const float* brow = bias + hc * 64;
        #pragma unroll
        for (int q = 0; q < 4; q++) {       // 4 x 16 cols
            float f[16];
            #pragma unroll
            for (int j = 0; j < 16; j++)
                f[j] = crow[q * 16 + j] + brow[q * 16 + j];
            uint4 u0, u1;
            *((__half2*)&u0.x) = __floats2half2_rn(f[0],  f[1]);
            *((__half2*)&u0.y) = __floats2half2_rn(f[2],  f[3]);
            *((__half2*)&u0.z) = __floats2half2_rn(f[4],  f[5]);
            *((__half2*)&u0.w) = __floats2half2_rn(f[6],  f[7]);
            *((__half2*)&u1.x) = __floats2half2_rn(f[8],  f[9]);
            *((__half2*)&u1.y) = __floats2half2_rn(f[10], f[11]);
            *((__half2*)&u1.z) = __floats2half2_rn(f[12], f[13]);
            *((__half2*)&u1.w) = __floats2half2_rn(f[14], f[15]);
            ((uint4*)&dstbuf[(long)grow * HF + hc * 64 + q * 16])[0] = u0;
            ((uint4*)&dstbuf[(long)grow * HF + hc * 64 + q * 16])[1] = u1;
        }
    }
}

// ---------------- projLin: feat_lin (N=32), scalar fp32 ----------------
#define BM 64
#define BK 32

__global__ __launch_bounds__(256, 2)
void projLin_kernel(const float* __restrict__ feat,
                    const float* __restrict__ Wlin, const float* __restrict__ blin,
                    float* __restrict__ out)
{
    __shared__ float As[BK][BM + 4];
    __shared__ float Bs[BK][F_DIM];

    int t  = threadIdx.x;
    int tx = t & 7;          // 8 col4 groups (32 cols)
    int ty = t >> 3;         // 32 row-groups of 2
    int rowBase = blockIdx.x * BM;

    float acc[2][4];
    #pragma unroll
    for (int i = 0; i < 2; i++)
        #pragma unroll
        for (int j = 0; j < 4; j++) acc[i][j] = 0.f;

    for (int k0 = 0; k0 < IN_DIM; k0 += BK) {
        #pragma unroll
        for (int i = 0; i < 2; i++) {
            int id = t + i * 256;
            int r  = id >> 3;
            int kq = id & 7;
            int grow = rowBase + r;
            float4 v = make_float4(0.f, 0.f, 0.f, 0.f);
            if (grow < N_NODES)
                v = ((const float4*)feat)[(long)grow * 32 + (k0 >> 2) + kq];
            As[kq * 4 + 0][r] = v.x;
            As[kq * 4 + 1][r] = v.y;
            As[kq * 4 + 2][r] = v.z;
            As[kq * 4 + 3][r] = v.w;
        }
        if (t < BK * F_DIM / 4) {
            int kk = t >> 3;
            int c4 = t & 7;
            *((float4*)&Bs[kk][c4 * 4]) =
                ((const float4*)Wlin)[(long)(k0 + kk) * (F_DIM / 4) + c4];
        }
        __syncthreads();

        #pragma unroll
        for (int k = 0; k < BK; k++) {
            float a0 = As[k][ty * 2];
            float a1 = As[k][ty * 2 + 1];
            float4 b = *((const float4*)&Bs[k][tx * 4]);
            acc[0][0] += a0 * b.x; acc[0][1] += a0 * b.y;
            acc[0][2] += a0 * b.z; acc[0][3] += a0 * b.w;
            acc[1][0] += a1 * b.x; acc[1][1] += a1 * b.y;
            acc[1][2] += a1 * b.z; acc[1][3] += a1 * b.w;
        }
        __syncthreads();
    }

    float4 b4 = ((const float4*)blin)[tx];
    #pragma unroll
    for (int i = 0; i < 2; i++) {
        int grow = rowBase + ty * 2 + i;
        if (grow >= N_NODES) continue;
        float4 v = make_float4(acc[i][0] + b4.x, acc[i][1] + b4.y,
                               acc[i][2] + b4.z, acc[i][3] + b4.w);
        ((float4*)out)[(long)grow * 40 + tx] = v;   // feat_lin -> out[:, 0, :]
    }
}

// ---------------- edge scores + denom ----------------
// FOUR edges per warp; lane l covers features 4l..4l+3, head = l>>3.
__global__ __launch_bounds__(256)
void edge_score_kernel(const void* __restrict__ srcp, const void* __restrict__ dstp,
                       const float* __restrict__ attn)
{
    int warp = (blockIdx.x * blockDim.x + threadIdx.x) >> 5;
    int lane = threadIdx.x & 31;
    int e0 = warp * 4;
    if (e0 >= N_EDGES) return;
    int is64 = g_idx64;

    long s[4], d[4];
    #pragma unroll
    for (int i = 0; i < 4; i++) {
        s[i] = load_index(srcp, e0 + i, is64);
        d[i] = load_index(dstp, e0 + i, is64);
    }

    float4 atf = ((const float4*)attn)[lane];
    __half2 a0 = __floats2half2_rn(atf.x, atf.y);
    __half2 a1 = __floats2half2_rn(atf.z, atf.w);
    const __half2 slope = __floats2half2_rn(NEG_SLOPE, NEG_SLOPE);

    uint2 ul[4], ur[4];
    #pragma unroll
    for (int i = 0; i < 4; i++) {
        ul[i] = ((const uint2*)g_el_mut)[s[i] * 32 + lane];
        ur[i] = ((const uint2*)g_er_mut)[d[i] * 32 + lane];
    }

    int h = lane >> 3;
    bool leader = (lane & 7) == 0;

    #pragma unroll
    for (int i = 0; i < 4; i++) {
        __half2 x0 = __hadd2(*((__half2*)&ul[i].x), *((__half2*)&ur[i].x));
        __half2 x1 = __hadd2(*((__half2*)&ul[i].y), *((__half2*)&ur[i].y));
        x0 = __hmax2(x0, __hmul2(x0, slope));          // leaky = max(x, 0.2x)
        x1 = __hmax2(x1, __hmul2(x1, slope));
        __half2 p2 = __hfma2(x1, a1, __hmul2(x0, a0));
        float2 pf = __half22float2(p2);
        float p = pf.x + pf.y;

        p += __shfl_xor_sync(0xFFFFFFFFu, p, 4);
        p += __shfl_xor_sync(0xFFFFFFFFu, p, 2);
        p += __shfl_xor_sync(0xFFFFFFFFu, p, 1);

        if (leader) {
            float e = __expf(p);   // softmax-invariant: segment_max skipped
            g_ex[(long)(e0 + i) * 4 + h] = e;
            float* dptr = &g_denom[d[i] * 4 + h];
            asm volatile("red.global.add.f32 [%0], %1;"
                         :: "l"(dptr), "f"(e) : "memory");
        }
    }
}

// ---------------- weighted aggregation ----------------
// FOUR edges per warp; fp16 gathers, fp32 math + RED.
__global__ __launch_bounds__(256)
void aggregate_kernel(const void* __restrict__ srcp, const void* __restrict__ dstp,
                      float* __restrict__ out)
{
    int warp = (blockIdx.x * blockDim.x + threadIdx.x) >> 5;
    int lane = threadIdx.x & 31;
    int e0 = warp * 4;
    if (e0 >= N_EDGES) return;
    int is64 = g_idx64;

    long s[4], d[4];
    #pragma unroll
    for (int i = 0; i < 4; i++) {
        s[i] = load_index(srcp, e0 + i, is64);
        d[i] = load_index(dstp, e0 + i, is64);
    }

    int h = lane >> 3;
    float ex[4], den[4];
    uint2 el[4];
    #pragma unroll
    for (int i = 0; i < 4; i++) {
        ex[i]  = g_ex[(long)(e0 + i) * 4 + h];
        den[i] = g_denom[d[i] * 4 + h];
        el[i]  = ((const uint2*)g_el_self_h)[s[i] * 32 + lane];
    }

    #pragma unroll
    for (int i = 0; i < 4; i++) {
        float a = ex[i] / den[i];
        float2 f0 = __half22float2(*((__half2*)&el[i].x));
        float2 f1 = __half22float2(*((__half2*)&el[i].y));
        float4 m = make_float4(f0.x * a, f0.y * a, f1.x * a, f1.y * a);
        float* p = out + (long)d[i] * OUT_ROW + 32 + lane * 4;
        asm volatile("red.global.add.v4.f32 [%0], {%1,%2,%3,%4};"
                     :: "l"(p), "f"(m.x), "f"(m.y), "f"(m.z), "f"(m.w) : "memory");
    }
}

// ---------------- stream fork resources (host-side, static init) ----------------
struct ForkResources {
    cudaStream_t s2;
    cudaEvent_t  e0, eZ, e2;
    bool ok;
    ForkResources() : ok(false) {
        if (cudaStreamCreateWithFlags(&s2, cudaStreamNonBlocking) != cudaSuccess) return;
        if (cudaEventCreateWithFlags(&e0, cudaEventDisableTiming) != cudaSuccess) return;
        if (cudaEventCreateWithFlags(&eZ, cudaEventDisableTiming) != cudaSuccess) return;
        if (cudaEventCreateWithFlags(&e2, cudaEventDisableTiming) != cudaSuccess) return;
        ok = true;
    }
};
static ForkResources g_fork;

// ---------------- launch ----------------
extern "C" void kernel_launch(void* const* d_in, const int* in_sizes, int n_in,
                              void* d_out, int out_size)
{
    const float* feat  = (const float*)d_in[0];
    const float* Wsrc  = (const float*)d_in[1];
    const float* bsrc  = (const float*)d_in[2];
    const float* Wdst  = (const float*)d_in[3];
    const float* bdst  = (const float*)d_in[4];
    const float* Wself = (const float*)d_in[5];
    const float* bself = (const float*)d_in[6];
    const float* Wlin  = (const float*)d_in[7];
    const float* blin  = (const float*)d_in[8];
    const float* attn  = (const float*)d_in[9];
    const void*  src   = d_in[10];
    const void*  dst   = d_in[11];
    float* out = (float*)d_out;

    dim3 pgW((N_NODES + 127) / 128, 3);             // 3 HF-wide GEMMs on tensor cores
    int linBlocks = (N_NODES + BM - 1) / BM;
    int edgeBlocks = (N_EDGES / 4 + 7) / 8;         // 4 edges/warp, 8 warps/block

    if (g_fork.ok) {
        // legal fork: s2 joins capture via event wait BEFORE receiving work
        cudaEventRecord(g_fork.e0, 0);
        cudaStreamWaitEvent(g_fork.s2, g_fork.e0, 0);

        // s2: zero + detect, then feat_lin (both independent of projW)
        zero_kernel<<<(N_NODES * 32 + 255) / 256, 256, 0, g_fork.s2>>>(
            (float4*)out, (const int*)src);
        cudaEventRecord(g_fork.eZ, g_fork.s2);
        projLin_kernel<<<linBlocks, 256, 0, g_fork.s2>>>(feat, Wlin, blin, out);
        cudaEventRecord(g_fork.e2, g_fork.s2);

        // main: all three HF projections on tensor cores
        projW_kernel<<<pgW, 256>>>(feat, Wsrc, bsrc, Wdst, bdst, Wself, bself);

        // main: edge_score (needs projW + zero/detect)
        cudaStreamWaitEvent(0, g_fork.eZ, 0);
        edge_score_kernel<<<edgeBlocks, 256>>>(src, dst, attn);

        // join projLin before aggregate (also joins s2 into the graph tail)
        cudaStreamWaitEvent(0, g_fork.e2, 0);
        aggregate_kernel<<<edgeBlocks, 256>>>(src, dst, out);
    } else {
        zero_kernel<<<(N_NODES * 32 + 255) / 256, 256>>>((float4*)out, (const int*)src);
        projW_kernel<<<pgW, 256>>>(feat, Wsrc, bsrc, Wdst, bdst, Wself, bself);
        projLin_kernel<<<linBlocks, 256>>>(feat, Wlin, blin, out);
        edge_score_kernel<<<edgeBlocks, 256>>>(src, dst, attn);
        aggregate_kernel<<<edgeBlocks, 256>>>(src, dst, out);
    }
}